// round 12
// baseline (speedup 1.0000x reference)
#include <cuda_runtime.h>
#include <math.h>

// ---------------- problem constants ----------------
#define T_STEPS 512
#define BATCH   256
#define FIN     64
#define HID     256
#define G3      768
#define ROWS_TOT (T_STEPS*BATCH)   // 131072

// recurrent kernel partitioning
#define R_GRID    128        // 8 batch tiles x 16 hidden tiles
#define R_THREADS 256        // 8 warps, 256 regs/thread budget
#define RB        32         // batch rows per CTA
#define WSTRIDE   264        // weight stride: 66 chunks/row -> 4-way-perfect weight wavefronts
#define INSTRIDE  260        // input stride: 65 chunks/row -> distinct input chunks w/ rotation
#define GSTRIDE   48         // gate result tile stride

// dynamic smem floats: 3 weight slices + 2 input tiles + 2 gate tiles + mask
#define R_SMEM_FLOATS (3*48*WSTRIDE + 2*RB*INSTRIDE + 2*RB*GSTRIDE + RB)
#define R_SMEM_BYTES  (R_SMEM_FLOATS*4)   // 231,040 B <= 232,448 opt-in max

// ---------------- device scratch (static: no allocs allowed) ----------------
__device__ float g_feats [(size_t)ROWS_TOT*HID];   // reused as value-net hidden
__device__ float g_gi0   [(size_t)ROWS_TOT*G3];    // layer0 gi incl b_ih0
__device__ float g_gruout[(size_t)ROWS_TOT*HID];
__device__ float g_hbuf  [2][2][BATCH][HID];       // [parity][layer][B][H] ping-pong
__device__ unsigned g_bar;

// ---------------- helpers ----------------
__device__ __forceinline__ float2 ffma2(float2 a, float2 b, float2 c) {
    unsigned long long au = *reinterpret_cast<unsigned long long*>(&a);
    unsigned long long bu = *reinterpret_cast<unsigned long long*>(&b);
    unsigned long long cu = *reinterpret_cast<unsigned long long*>(&c);
    unsigned long long du;
    asm("fma.rn.f32x2 %0, %1, %2, %3;" : "=l"(du) : "l"(au), "l"(bu), "l"(cu));
    return *reinterpret_cast<float2*>(&du);
}

__device__ __forceinline__ float sigmoidf_(float x) { return 1.0f / (1.0f + __expf(-x)); }

// local weight-row (0..47) -> global gate row for hidden base hb
__device__ __forceinline__ int grow_map(int hb, int c) {
    return (c < 16) ? (hb + c) : (c < 32) ? (256 + hb + (c - 16)) : (512 + hb + (c - 32));
}

__global__ void init_bar_kernel() { g_bar = 0u; }

// ---------------- generic tiled fp32 GEMM: C = act(A[M,K] @ W[N,K]^T + bias) ----------------
template <bool LRELU>
__global__ void __launch_bounds__(128) gemm_lin_kernel(
    const float* __restrict__ A, const float* __restrict__ W,
    const float* __restrict__ bias, float* __restrict__ C,
    int M, int N, int K)
{
    __shared__ __align__(16) float As[16][68];
    __shared__ __align__(16) float Bs[16][68];

    const int tid  = threadIdx.x;
    const int row0 = blockIdx.y * 64;
    const int col0 = blockIdx.x * 64;
    const int c0 = (tid & 15) * 4;
    const int r0 = (tid >> 4) * 8;

    float2 acc[4][4];
#pragma unroll
    for (int i = 0; i < 4; i++)
#pragma unroll
        for (int j = 0; j < 4; j++) acc[i][j] = make_float2(0.f, 0.f);

    for (int kt = 0; kt < K; kt += 16) {
#pragma unroll
        for (int i = 0; i < 2; i++) {
            int e  = tid + i * 128;
            int r  = e >> 2;
            int k4 = (e & 3) * 4;
            float4 va = *(const float4*)&A[(size_t)(row0 + r) * K + kt + k4];
            As[k4 + 0][r] = va.x; As[k4 + 1][r] = va.y; As[k4 + 2][r] = va.z; As[k4 + 3][r] = va.w;
            float4 vb = *(const float4*)&W[(size_t)(col0 + r) * K + kt + k4];
            Bs[k4 + 0][r] = vb.x; Bs[k4 + 1][r] = vb.y; Bs[k4 + 2][r] = vb.z; Bs[k4 + 3][r] = vb.w;
        }
        __syncthreads();
#pragma unroll
        for (int k = 0; k < 16; k++) {
            float4 a03 = *(const float4*)&As[k][r0];
            float4 a47 = *(const float4*)&As[k][r0 + 4];
            float4 b   = *(const float4*)&Bs[k][c0];
            float2 ap[4] = { make_float2(a03.x, a03.y), make_float2(a03.z, a03.w),
                             make_float2(a47.x, a47.y), make_float2(a47.z, a47.w) };
            float2 bd[4] = { make_float2(b.x, b.x), make_float2(b.y, b.y),
                             make_float2(b.z, b.z), make_float2(b.w, b.w) };
#pragma unroll
            for (int i = 0; i < 4; i++)
#pragma unroll
                for (int j = 0; j < 4; j++) acc[i][j] = ffma2(ap[i], bd[j], acc[i][j]);
        }
        __syncthreads();
    }

#pragma unroll
    for (int j = 0; j < 4; j++) {
        float bv = bias[col0 + c0 + j];
#pragma unroll
        for (int i = 0; i < 4; i++) {
            float v0 = acc[i][j].x + bv;
            float v1 = acc[i][j].y + bv;
            if (LRELU) { v0 = (v0 > 0.f) ? v0 : 0.01f * v0; v1 = (v1 > 0.f) ? v1 : 0.01f * v1; }
            C[(size_t)(row0 + r0 + 2 * i    ) * N + col0 + c0 + j] = v0;
            C[(size_t)(row0 + r0 + 2 * i + 1) * N + col0 + c0 + j] = v1;
        }
    }
}

// ---------------- recurrent tile GEMM (256 thr): out[32][48] = in[32][256] @ w[48][256]^T ----
// 8 warps. Warp w: rows (w>>1)*8..+7, cols (w&1)*24..+23.
// Lane: kc = lane>>2 (split-K-8, 32-float chunks), s = lane&3 (col-group of 6).
// Thread tile 8 rows x 6 cols over K-chunk kc -> per 4-k: 14 LDS.128 feed 192 FMAs.
// LDS.128 instrs/warp/gemm = 8 iters * 14 = 112 (vs 80 at tile 4x6 with 16 warps,
// but warp count halves: 3584 cyc/gemm crossbar vs 5120).
// kk rotation 4*((kc+it)&7) de-phases the 8 kc chunks; WSTRIDE=264 spreads weight
// wavefronts perfectly 4-way. Reduction: 3x shfl_xor (4,8,16); every lane ends with
// full sums; lane (kc,s) writes row kc of its row-group, cols s*6..+5.
__device__ __forceinline__ void gemm_tile(const float* __restrict__ in_s,
                                          const float* __restrict__ w_s,
                                          float* __restrict__ out_s,
                                          const float* __restrict__ bias6,
                                          int tid)
{
    const int lane = tid & 31;
    const int warp = tid >> 5;            // 0..7
    const int kc   = lane >> 2;           // 0..7
    const int s    = lane & 3;            // 0..3
    const int row0 = (warp >> 1) * 8;     // 0,8,16,24
    const int col0 = (warp & 1) * 24 + s * 6;

    const float* pin = in_s + (size_t)row0 * INSTRIDE + kc * 32;
    const float* pw  = w_s  + (size_t)col0 * WSTRIDE  + kc * 32;

    float2 acc[8][6];
#pragma unroll
    for (int i = 0; i < 8; i++)
#pragma unroll
        for (int j = 0; j < 6; j++) acc[i][j] = make_float2(0.f, 0.f);

#pragma unroll
    for (int it = 0; it < 8; it++) {
        const int kk = 4 * ((kc + it) & 7);   // rotation: distinct chunks across kc
        float4 x[8];
#pragma unroll
        for (int i = 0; i < 8; i++) x[i] = *(const float4*)(pin + i * INSTRIDE + kk);
#pragma unroll
        for (int j = 0; j < 6; j++) {
            float4 wv = *(const float4*)(pw + j * WSTRIDE + kk);
            float2 wl = make_float2(wv.x, wv.y);
            float2 wh = make_float2(wv.z, wv.w);
#pragma unroll
            for (int i = 0; i < 8; i++) {
                acc[i][j] = ffma2(make_float2(x[i].x, x[i].y), wl, acc[i][j]);
                acc[i][j] = ffma2(make_float2(x[i].z, x[i].w), wh, acc[i][j]);
            }
        }
    }

    // butterfly-reduce across the 8 kc lanes (strides 4,8,16); all lanes get sums.
    // writer: lane (kc,s) stores row row0+kc, cols col0..col0+5.
    float outv[6];
#pragma unroll
    for (int j = 0; j < 6; j++) {
        float best;
#pragma unroll
        for (int i = 0; i < 8; i++) {
            float v = acc[i][j].x + acc[i][j].y;
            v += __shfl_xor_sync(0xffffffffu, v, 4);
            v += __shfl_xor_sync(0xffffffffu, v, 8);
            v += __shfl_xor_sync(0xffffffffu, v, 16);
            if (i == kc) best = v;
        }
        outv[j] = best + bias6[j];
    }
#pragma unroll
    for (int j = 0; j < 6; j += 2)
        *(float2*)&out_s[(row0 + kc) * GSTRIDE + col0 + j] = make_float2(outv[j], outv[j + 1]);
}

// ---------------- persistent recurrent kernel ----------------
// blk = bt*16 + ct ; bt = batch tile (32 rows), ct = hidden tile (16 units -> 48 gate rows)
__global__ void __launch_bounds__(R_THREADS, 1) recurrent_kernel(
    const int*   __restrict__ dones,
    const float* __restrict__ w_ih,   // [2][768][256]
    const float* __restrict__ w_hh,   // [2][768][256]
    const float* __restrict__ b_ih,   // [2][768]
    const float* __restrict__ b_hh)   // [2][768]
{
    extern __shared__ __align__(16) float smem[];
    float* w0s   = smem;                       // w_hh0 slice [48][WSTRIDE]
    float* w1s   = w0s + 48 * WSTRIDE;         // w_ih1 slice
    float* w2s   = w1s + 48 * WSTRIDE;         // w_hh1 slice
    float* inA   = w2s + 48 * WSTRIDE;         // [32][INSTRIDE]
    float* inB   = inA + RB * INSTRIDE;        // [32][INSTRIDE]
    float* outA  = inB + RB * INSTRIDE;        // [32][GSTRIDE]
    float* outB  = outA + RB * GSTRIDE;        // [32][GSTRIDE]
    float* smask = outB + RB * GSTRIDE;        // [32]

    const int tid = threadIdx.x;
    const int bt  = blockIdx.x >> 4;
    const int ct  = blockIdx.x & 15;
    const int b0  = bt * RB;
    const int hb  = ct * 16;

    const float* w_hh0 = w_hh;
    const float* w_ih1 = w_ih + 768 * 256;
    const float* w_hh1 = w_hh + 768 * 256;

    // ---- load persistent weight slices (resident in smem for all 512 steps) ----
    for (int idx = tid; idx < 48 * (HID / 4); idx += R_THREADS) {
        int c = idx >> 6, k4 = idx & 63;
        int gr = grow_map(hb, c);
        *(float4*)&w0s[c * WSTRIDE + k4 * 4] = *(const float4*)&w_hh0[gr * HID + k4 * 4];
        *(float4*)&w1s[c * WSTRIDE + k4 * 4] = *(const float4*)&w_ih1[gr * HID + k4 * 4];
        *(float4*)&w2s[c * WSTRIDE + k4 * 4] = *(const float4*)&w_hh1[gr * HID + k4 * 4];
    }
    __syncthreads();

    // ---- hoist biases for this thread's writer columns (step-invariant) ----
    float bias0[6], bias1[6], bias2[6];
    {
        int col0 = ((tid >> 5) & 1) * 24 + (tid & 3) * 6;
#pragma unroll
        for (int j = 0; j < 6; j++) {
            int gc = grow_map(hb, col0 + j);
            bias0[j] = __ldg(&b_hh[gc]);
            bias1[j] = __ldg(&b_ih[768 + gc]);
            bias2[j] = __ldg(&b_hh[768 + gc]);
        }
    }

    // gate-unit mapping: 256 threads -> two (row, j) units each
    const int grow0 = tid >> 4,          gj0 = tid & 15;
    const int grow1 = (tid + 256) >> 4;  // gj1 == gj0

    for (int t = 0; t < T_STEPS; t++) {
        const int rp = t & 1, wp = rp ^ 1;

        // ---- prefetch gi0 for this step's gates (DRAM, no reuse -> start early) ----
        size_t gb0 = ((size_t)t * BATCH + b0 + grow0) * G3 + hb + gj0;
        size_t gb1 = ((size_t)t * BATCH + b0 + grow1) * G3 + hb + gj0;
        float p_r0 = __ldcs(&g_gi0[gb0]);
        float p_z0 = __ldcs(&g_gi0[gb0 + 256]);
        float p_n0 = __ldcs(&g_gi0[gb0 + 512]);
        float p_r1 = __ldcs(&g_gi0[gb1]);
        float p_z1 = __ldcs(&g_gi0[gb1 + 256]);
        float p_n1 = __ldcs(&g_gi0[gb1 + 512]);

        // ---- done masks for this step ----
        if (tid < RB) smask[tid] = 1.0f - (float)dones[t * BATCH + b0 + tid];
        __syncthreads();

        // ===== phase 1: layer 0 =====
        // inA = mask * h0_prev
        for (int idx = tid; idx < RB * HID / 4; idx += R_THREADS) {
            int row = idx >> 6, k4 = idx & 63;
            float4 v = __ldcg((const float4*)&g_hbuf[rp][0][b0 + row][k4 * 4]);
            float m = smask[row];
            v.x *= m; v.y *= m; v.z *= m; v.w *= m;
            *(float4*)&inA[row * INSTRIDE + k4 * 4] = v;
        }
        __syncthreads();

        gemm_tile(inA, w0s, outA, bias0, tid);   // gh0 tile
        __syncthreads();

        // gates layer 0: two units per thread, prefetched gi
        {
            float gh_r = outA[grow0 * GSTRIDE + gj0];
            float gh_z = outA[grow0 * GSTRIDE + 16 + gj0];
            float gh_n = outA[grow0 * GSTRIDE + 32 + gj0];
            float r = sigmoidf_(p_r0 + gh_r);
            float z = sigmoidf_(p_z0 + gh_z);
            float n = tanhf(p_n0 + r * gh_n);
            float hm = inA[grow0 * INSTRIDE + hb + gj0];    // already masked
            __stcg(&g_hbuf[wp][0][b0 + grow0][hb + gj0], (1.0f - z) * n + z * hm);

            gh_r = outA[grow1 * GSTRIDE + gj0];
            gh_z = outA[grow1 * GSTRIDE + 16 + gj0];
            gh_n = outA[grow1 * GSTRIDE + 32 + gj0];
            r = sigmoidf_(p_r1 + gh_r);
            z = sigmoidf_(p_z1 + gh_z);
            n = tanhf(p_n1 + r * gh_n);
            hm = inA[grow1 * INSTRIDE + hb + gj0];
            __stcg(&g_hbuf[wp][0][b0 + grow1][hb + gj0], (1.0f - z) * n + z * hm);
        }

        // ---- single grid barrier per step (phase1 -> phase2) ----
        // All cross-step hazards transitively ordered by this barrier (R5 matrix).
        __syncthreads();
        if (tid == 0) {
            __threadfence();
            atomicAdd(&g_bar, 1u);
            unsigned target = (unsigned)(t + 1) * R_GRID;
            while (*((volatile unsigned*)&g_bar) < target) __nanosleep(32);
            __threadfence();
        }
        __syncthreads();

        // ===== phase 2: layer 1 =====
        // inA = h0_new (no mask), inB = mask * h1_prev
        for (int idx = tid; idx < RB * HID / 4; idx += R_THREADS) {
            int row = idx >> 6, k4 = idx & 63;
            float4 v = __ldcg((const float4*)&g_hbuf[wp][0][b0 + row][k4 * 4]);
            *(float4*)&inA[row * INSTRIDE + k4 * 4] = v;
            float4 u = __ldcg((const float4*)&g_hbuf[rp][1][b0 + row][k4 * 4]);
            float m = smask[row];
            u.x *= m; u.y *= m; u.z *= m; u.w *= m;
            *(float4*)&inB[row * INSTRIDE + k4 * 4] = u;
        }
        __syncthreads();

        gemm_tile(inA, w1s, outA, bias1, tid);   // gi1 tile
        gemm_tile(inB, w2s, outB, bias2, tid);   // gh1 tile
        __syncthreads();

        // gates layer 1: two units per thread
#pragma unroll
        for (int i = 0; i < 2; i++) {
            int row = (i == 0) ? grow0 : grow1;
            float gi_r = outA[row * GSTRIDE + gj0];
            float gi_z = outA[row * GSTRIDE + 16 + gj0];
            float gi_n = outA[row * GSTRIDE + 32 + gj0];
            float gh_r = outB[row * GSTRIDE + gj0];
            float gh_z = outB[row * GSTRIDE + 16 + gj0];
            float gh_n = outB[row * GSTRIDE + 32 + gj0];
            float r = sigmoidf_(gi_r + gh_r);
            float z = sigmoidf_(gi_z + gh_z);
            float n = tanhf(gi_n + r * gh_n);
            float hm = inB[row * INSTRIDE + hb + gj0];     // masked h1_prev
            float hnew = (1.0f - z) * n + z * hm;
            __stcg(&g_hbuf[wp][1][b0 + row][hb + gj0], hnew);
            g_gruout[((size_t)t * BATCH + b0 + row) * HID + hb + gj0] = hnew;
        }
        __syncthreads();
    }
}

// ---------------- value head final reduction: v = hidden @ w_v2^T + b_v2 ----------------
__global__ void __launch_bounds__(256) vhead_kernel(
    const float* __restrict__ hidden, const float* __restrict__ w_v2,
    const float* __restrict__ b_v2, float* __restrict__ out)
{
    int row  = blockIdx.x * 8 + (threadIdx.x >> 5);
    int lane = threadIdx.x & 31;
    const float4* hp = (const float4*)(hidden + (size_t)row * HID);
    const float4* wp = (const float4*)w_v2;
    float s = 0.f;
#pragma unroll
    for (int i = 0; i < 2; i++) {
        float4 h4 = hp[lane * 2 + i];
        float4 w4 = __ldg(&wp[lane * 2 + i]);
        s += h4.x * w4.x + h4.y * w4.y + h4.z * w4.z + h4.w * w4.w;
    }
#pragma unroll
    for (int off = 16; off; off >>= 1) s += __shfl_xor_sync(0xffffffffu, s, off);
    if (lane == 0) out[row] = s + b_v2[0];
}

// ---------------- launch ----------------
extern "C" void kernel_launch(void* const* d_in, const int* in_sizes, int n_in,
                              void* d_out, int out_size) {
    const float* x        = (const float*)d_in[0];
    const int*   dones    = (const int*)  d_in[1];
    const float* h0       = (const float*)d_in[2];
    const float* w_shared = (const float*)d_in[3];
    const float* b_shared = (const float*)d_in[4];
    const float* w_ih     = (const float*)d_in[5];
    const float* w_hh     = (const float*)d_in[6];
    const float* b_ih     = (const float*)d_in[7];
    const float* b_hh     = (const float*)d_in[8];
    const float* w_v1     = (const float*)d_in[9];
    const float* b_v1     = (const float*)d_in[10];
    const float* w_v2     = (const float*)d_in[11];
    const float* b_v2     = (const float*)d_in[12];
    float* out = (float*)d_out;

    // idempotent, capture-safe (not a stream op)
    cudaFuncSetAttribute(recurrent_kernel,
                         cudaFuncAttributeMaxDynamicSharedMemorySize, R_SMEM_BYTES);

    float* featsP;  cudaGetSymbolAddress((void**)&featsP,  g_feats);
    float* gi0P;    cudaGetSymbolAddress((void**)&gi0P,    g_gi0);
    float* gruoutP; cudaGetSymbolAddress((void**)&gruoutP, g_gruout);
    float* hiddenP = featsP;   // overlay: feats is dead after gi0 GEMM

    // reset barrier + seed h ping-pong (parity 0) with h0
    init_bar_kernel<<<1, 1>>>();
    cudaMemcpyToSymbolAsync(g_hbuf, h0, (size_t)2 * BATCH * HID * sizeof(float),
                            0, cudaMemcpyDeviceToDevice, 0);

    // feats = LReLU(x @ w_shared^T + b_shared)  [131072, 256]
    {
        dim3 g(HID / 64, ROWS_TOT / 64);
        gemm_lin_kernel<true><<<g, 128>>>(x, w_shared, b_shared, featsP,
                                          ROWS_TOT, HID, FIN);
    }
    // gi0 = feats @ w_ih0^T + b_ih0  [131072, 768]
    {
        dim3 g(G3 / 64, ROWS_TOT / 64);
        gemm_lin_kernel<false><<<g, 128>>>(featsP, w_ih, b_ih, gi0P,
                                           ROWS_TOT, G3, HID);
    }
    // sequential GRU rollout (persistent, grid-resident)
    recurrent_kernel<<<R_GRID, R_THREADS, R_SMEM_BYTES>>>(dones, w_ih, w_hh, b_ih, b_hh);

    // hidden = LReLU(gruout @ w_v1^T + b_v1)   (overwrites g_feats)
    {
        dim3 g(HID / 64, ROWS_TOT / 64);
        gemm_lin_kernel<true><<<g, 128>>>(gruoutP, w_v1, b_v1, hiddenP,
                                          ROWS_TOT, HID, HID);
    }
    // v = hidden @ w_v2^T + b_v2  -> out[0 : 131072)
    vhead_kernel<<<ROWS_TOT / 8, 256>>>(hiddenP, w_v2, b_v2, out);

    // h_final lives in parity 0 after 512 steps -> out[131072 : 262144)
    if (out_size >= 2 * ROWS_TOT) {
        cudaMemcpyFromSymbolAsync(out + ROWS_TOT, g_hbuf,
                                  (size_t)2 * BATCH * HID * sizeof(float),
                                  0, cudaMemcpyDeviceToDevice, 0);
    }
}

// round 15
// speedup vs baseline: 1.1451x; 1.1451x over previous
#include <cuda_runtime.h>
#include <cuda_fp16.h>
#include <math.h>

// ---------------- problem constants ----------------
#define T_STEPS 512
#define BATCH   256
#define FIN     64
#define HID     256
#define G3      768
#define ROWS_TOT (T_STEPS*BATCH)   // 131072

// recurrent kernel partitioning (R11 skeleton: 16 warps, 4x6 tile, split-K-8)
#define R_GRID    128        // 8 batch tiles x 16 hidden tiles
#define R_THREADS 512        // 16 warps -> 4 per SMSP (latency hiding, proven)
#define RB        32         // batch rows per CTA
#define WSTRIDE_U 132        // weight smem stride in uints (264 fp16 = 528 B, 33 uint4 chunks)
#define INSTRIDE  260        // input stride (floats)
#define GSTRIDE   49         // gate result tile stride

// dynamic smem floats: 3 fp16 weight slices (as uint) + 2 input tiles + 2 gate tiles + mask
#define R_SMEM_FLOATS (3*48*WSTRIDE_U + 2*RB*INSTRIDE + 2*RB*GSTRIDE + RB)
#define R_SMEM_BYTES  (R_SMEM_FLOATS*4)   // 155,264 B

// ---------------- device scratch (static: no allocs allowed) ----------------
__device__ float g_feats [(size_t)ROWS_TOT*HID];   // reused as value-net hidden
__device__ float g_gi0   [(size_t)ROWS_TOT*G3];    // layer0 gi incl b_ih0 (fp32, exact)
__device__ float g_gruout[(size_t)ROWS_TOT*HID];
__device__ float g_hbuf  [2][2][BATCH][HID];       // [parity][layer][B][H] ping-pong
__device__ unsigned g_bar;

// ---------------- helpers ----------------
__device__ __forceinline__ float2 ffma2(float2 a, float2 b, float2 c) {
    unsigned long long au = *reinterpret_cast<unsigned long long*>(&a);
    unsigned long long bu = *reinterpret_cast<unsigned long long*>(&b);
    unsigned long long cu = *reinterpret_cast<unsigned long long*>(&c);
    unsigned long long du;
    asm("fma.rn.f32x2 %0, %1, %2, %3;" : "=l"(du) : "l"(au), "l"(bu), "l"(cu));
    return *reinterpret_cast<float2*>(&du);
}

__device__ __forceinline__ float sigmoidf_(float x) { return 1.0f / (1.0f + __expf(-x)); }

// pack two fp32 -> fp16x2 (RNE); weights ~N(0,0.05): no overflow, tail subnormals OK
__device__ __forceinline__ unsigned pack_f16x2(float lo, float hi) {
    __half2 h = __floats2half2_rn(lo, hi);
    return *reinterpret_cast<unsigned*>(&h);
}

// unpack fp16x2 -> float2 (exact widening converts)
__device__ __forceinline__ float2 h2f2(unsigned v) {
    __half2 h = *reinterpret_cast<__half2*>(&v);
    return __half22float2(h);
}

// local weight-row (0..47) -> global gate row for hidden base hb
__device__ __forceinline__ int grow_map(int hb, int c) {
    return (c < 16) ? (hb + c) : (c < 32) ? (256 + hb + (c - 16)) : (512 + hb + (c - 32));
}

__global__ void init_bar_kernel() { g_bar = 0u; }

// ---------------- generic tiled fp32 GEMM: C = act(A[M,K] @ W[N,K]^T + bias) ----------------
template <bool LRELU>
__global__ void __launch_bounds__(128) gemm_lin_kernel(
    const float* __restrict__ A, const float* __restrict__ W,
    const float* __restrict__ bias, float* __restrict__ C,
    int M, int N, int K)
{
    __shared__ __align__(16) float As[16][68];
    __shared__ __align__(16) float Bs[16][68];

    const int tid  = threadIdx.x;
    const int row0 = blockIdx.y * 64;
    const int col0 = blockIdx.x * 64;
    const int c0 = (tid & 15) * 4;
    const int r0 = (tid >> 4) * 8;

    float2 acc[4][4];
#pragma unroll
    for (int i = 0; i < 4; i++)
#pragma unroll
        for (int j = 0; j < 4; j++) acc[i][j] = make_float2(0.f, 0.f);

    for (int kt = 0; kt < K; kt += 16) {
#pragma unroll
        for (int i = 0; i < 2; i++) {
            int e  = tid + i * 128;
            int r  = e >> 2;
            int k4 = (e & 3) * 4;
            float4 va = *(const float4*)&A[(size_t)(row0 + r) * K + kt + k4];
            As[k4 + 0][r] = va.x; As[k4 + 1][r] = va.y; As[k4 + 2][r] = va.z; As[k4 + 3][r] = va.w;
            float4 vb = *(const float4*)&W[(size_t)(col0 + r) * K + kt + k4];
            Bs[k4 + 0][r] = vb.x; Bs[k4 + 1][r] = vb.y; Bs[k4 + 2][r] = vb.z; Bs[k4 + 3][r] = vb.w;
        }
        __syncthreads();
#pragma unroll
        for (int k = 0; k < 16; k++) {
            float4 a03 = *(const float4*)&As[k][r0];
            float4 a47 = *(const float4*)&As[k][r0 + 4];
            float4 b   = *(const float4*)&Bs[k][c0];
            float2 ap[4] = { make_float2(a03.x, a03.y), make_float2(a03.z, a03.w),
                             make_float2(a47.x, a47.y), make_float2(a47.z, a47.w) };
            float2 bd[4] = { make_float2(b.x, b.x), make_float2(b.y, b.y),
                             make_float2(b.z, b.z), make_float2(b.w, b.w) };
#pragma unroll
            for (int i = 0; i < 4; i++)
#pragma unroll
                for (int j = 0; j < 4; j++) acc[i][j] = ffma2(ap[i], bd[j], acc[i][j]);
        }
        __syncthreads();
    }

#pragma unroll
    for (int j = 0; j < 4; j++) {
        float bv = bias[col0 + c0 + j];
#pragma unroll
        for (int i = 0; i < 4; i++) {
            float v0 = acc[i][j].x + bv;
            float v1 = acc[i][j].y + bv;
            if (LRELU) { v0 = (v0 > 0.f) ? v0 : 0.01f * v0; v1 = (v1 > 0.f) ? v1 : 0.01f * v1; }
            C[(size_t)(row0 + r0 + 2 * i    ) * N + col0 + c0 + j] = v0;
            C[(size_t)(row0 + r0 + 2 * i + 1) * N + col0 + c0 + j] = v1;
        }
    }
}

// ---------------- recurrent tile GEMM (512 thr): out[32][48] = in[32][256] @ w[48][256]^T ----
// 16 warps; warp w: rows (w>>1)*4..+3, colgroup cg=(w&1)*4+s; lane kc = split-K-8 chunk.
// WEIGHTS ARE FP16X2 in smem: one LDS.128 = 8 weights -> per it (8 k-values):
// 8 input LDS + 6 weight LDS = 14 instrs feed 96 FFMA2. 4 its -> 56 LDS.128/warp/gemm
// (was 80 with fp32 weights). Unpack: 2x cvt.f32.f16 per uint (fixed-lat F2F).
// Rotation (it+kc)&3 de-phases kc chunks. Reduction: 3x shfl_xor; kc==0 writes.
__device__ __forceinline__ void gemm_tile(const float* __restrict__ in_s,
                                          const unsigned* __restrict__ w_s,
                                          float* __restrict__ out_s,
                                          const float* __restrict__ bias_g,
                                          int hb, int tid)
{
    const int lane = tid & 31;
    const int warp = tid >> 5;            // 0..15
    const int kc   = lane >> 2;           // 0..7 (32-float K chunk)
    const int s    = lane & 3;
    const int rg   = warp >> 1;           // 0..7 -> rows rg*4..+3
    const int cg   = (warp & 1) * 4 + s;  // 0..7 -> cols cg*6..+5
    const int c0   = cg * 6;

    const float*    pin = in_s + (size_t)(rg * 4) * INSTRIDE + kc * 32;
    const unsigned* pw  = w_s  + (size_t)c0 * WSTRIDE_U + kc * 16;

    float2 acc[4][6];
#pragma unroll
    for (int i = 0; i < 4; i++)
#pragma unroll
        for (int j = 0; j < 6; j++) acc[i][j] = make_float2(0.f, 0.f);

#pragma unroll
    for (int it = 0; it < 4; it++) {
        const int r4 = (it + kc) & 3;     // rotation: de-phase kc chunks
        const int ko = r4 * 8;            // 8 k-values per iteration
        float4 xa[4], xb[4];
#pragma unroll
        for (int i = 0; i < 4; i++) {
            xa[i] = *(const float4*)(pin + i * INSTRIDE + ko);
            xb[i] = *(const float4*)(pin + i * INSTRIDE + ko + 4);
        }
#pragma unroll
        for (int j = 0; j < 6; j++) {
            uint4 wv = *(const uint4*)(pw + j * WSTRIDE_U + r4 * 4);
            float2 w0 = h2f2(wv.x);
            float2 w1 = h2f2(wv.y);
            float2 w2 = h2f2(wv.z);
            float2 w3 = h2f2(wv.w);
#pragma unroll
            for (int i = 0; i < 4; i++) {
                acc[i][j] = ffma2(make_float2(xa[i].x, xa[i].y), w0, acc[i][j]);
                acc[i][j] = ffma2(make_float2(xa[i].z, xa[i].w), w1, acc[i][j]);
                acc[i][j] = ffma2(make_float2(xb[i].x, xb[i].y), w2, acc[i][j]);
                acc[i][j] = ffma2(make_float2(xb[i].z, xb[i].w), w3, acc[i][j]);
            }
        }
    }

    // butterfly-reduce across the 8 kc lanes (strides 4,8,16); kc==0 lanes write.
    float red[4][6];
#pragma unroll
    for (int i = 0; i < 4; i++)
#pragma unroll
        for (int j = 0; j < 6; j++) {
            float v = acc[i][j].x + acc[i][j].y;
            v += __shfl_xor_sync(0xffffffffu, v, 4);
            v += __shfl_xor_sync(0xffffffffu, v, 8);
            v += __shfl_xor_sync(0xffffffffu, v, 16);
            red[i][j] = v;
        }

    if (kc == 0) {
#pragma unroll
        for (int j = 0; j < 6; j++) {
            float bb = __ldg(&bias_g[grow_map(hb, c0 + j)]);
#pragma unroll
            for (int i = 0; i < 4; i++)
                out_s[(rg * 4 + i) * GSTRIDE + c0 + j] = red[i][j] + bb;
        }
    }
}

// ---------------- persistent recurrent kernel ----------------
// blk = bt*16 + ct ; bt = batch tile (32 rows), ct = hidden tile (16 units -> 48 gate rows)
__global__ void __launch_bounds__(R_THREADS, 1) recurrent_kernel(
    const int*   __restrict__ dones,
    const float* __restrict__ w_ih,   // [2][768][256]
    const float* __restrict__ w_hh,   // [2][768][256]
    const float* __restrict__ b_ih,   // [2][768]
    const float* __restrict__ b_hh)   // [2][768]
{
    extern __shared__ __align__(16) float smem[];
    unsigned* w0s = (unsigned*)smem;            // w_hh0 slice, fp16x2 [48][WSTRIDE_U]
    unsigned* w1s = w0s + 48 * WSTRIDE_U;       // w_ih1 slice
    unsigned* w2s = w1s + 48 * WSTRIDE_U;       // w_hh1 slice
    float* inA    = (float*)(w2s + 48 * WSTRIDE_U);  // [32][INSTRIDE]
    float* inB    = inA + RB * INSTRIDE;        // [32][INSTRIDE]
    float* outA   = inB + RB * INSTRIDE;        // [32][GSTRIDE]
    float* outB   = outA + RB * GSTRIDE;        // [32][GSTRIDE]
    float* smask  = outB + RB * GSTRIDE;        // [32]

    const int tid = threadIdx.x;
    const int bt  = blockIdx.x >> 4;
    const int ct  = blockIdx.x & 15;
    const int b0  = bt * RB;
    const int hb  = ct * 16;

    const float* w_hh0 = w_hh;
    const float* w_ih1 = w_ih + 768 * 256;
    const float* w_hh1 = w_hh + 768 * 256;
    const float* b_hh0 = b_hh;
    const float* b_ih1 = b_ih + 768;
    const float* b_hh1 = b_hh + 768;

    // ---- load + quantize persistent weight slices to fp16x2 (resident all 512 steps) ----
    for (int idx = tid; idx < 48 * 32; idx += R_THREADS) {   // 32 granules of 8 fp32 per row
        int c = idx >> 5, g = idx & 31;
        int gr = grow_map(hb, c);
        const float4* s0 = (const float4*)&w_hh0[(size_t)gr * HID + g * 8];
        float4 a = s0[0], b = s0[1];
        ((uint4*)&w0s[c * WSTRIDE_U])[g] =
            make_uint4(pack_f16x2(a.x, a.y), pack_f16x2(a.z, a.w),
                       pack_f16x2(b.x, b.y), pack_f16x2(b.z, b.w));
        const float4* s1 = (const float4*)&w_ih1[(size_t)gr * HID + g * 8];
        a = s1[0]; b = s1[1];
        ((uint4*)&w1s[c * WSTRIDE_U])[g] =
            make_uint4(pack_f16x2(a.x, a.y), pack_f16x2(a.z, a.w),
                       pack_f16x2(b.x, b.y), pack_f16x2(b.z, b.w));
        const float4* s2 = (const float4*)&w_hh1[(size_t)gr * HID + g * 8];
        a = s2[0]; b = s2[1];
        ((uint4*)&w2s[c * WSTRIDE_U])[g] =
            make_uint4(pack_f16x2(a.x, a.y), pack_f16x2(a.z, a.w),
                       pack_f16x2(b.x, b.y), pack_f16x2(b.z, b.w));
    }
    __syncthreads();

    // gate-unit mapping: 512 threads -> exactly one (row, j) unit each
    const int grow0 = tid >> 4, gj0 = tid & 15;

    for (int t = 0; t < T_STEPS; t++) {
        const int rp = t & 1, wp = rp ^ 1;

        // ---- prefetch gi0 for this step's gate (DRAM, no reuse -> start early) ----
        size_t gb0 = ((size_t)t * BATCH + b0 + grow0) * G3 + hb + gj0;
        float p_r0 = __ldcs(&g_gi0[gb0]);
        float p_z0 = __ldcs(&g_gi0[gb0 + 256]);
        float p_n0 = __ldcs(&g_gi0[gb0 + 512]);

        // ---- done masks for this step ----
        if (tid < RB) smask[tid] = 1.0f - (float)dones[t * BATCH + b0 + tid];
        __syncthreads();

        // ===== phase 1: layer 0 =====
        // inA = mask * h0_prev
        for (int idx = tid; idx < RB * HID / 4; idx += R_THREADS) {
            int row = idx >> 6, k4 = idx & 63;
            float4 v = __ldcg((const float4*)&g_hbuf[rp][0][b0 + row][k4 * 4]);
            float m = smask[row];
            v.x *= m; v.y *= m; v.z *= m; v.w *= m;
            *(float4*)&inA[row * INSTRIDE + k4 * 4] = v;
        }
        __syncthreads();

        gemm_tile(inA, w0s, outA, b_hh0, hb, tid);   // gh0 tile
        __syncthreads();

        // gates layer 0: one unit per thread, prefetched gi
        {
            float gh_r = outA[grow0 * GSTRIDE + gj0];
            float gh_z = outA[grow0 * GSTRIDE + 16 + gj0];
            float gh_n = outA[grow0 * GSTRIDE + 32 + gj0];
            float r = sigmoidf_(p_r0 + gh_r);
            float z = sigmoidf_(p_z0 + gh_z);
            float n = tanhf(p_n0 + r * gh_n);
            float hm = inA[grow0 * INSTRIDE + hb + gj0];    // already masked
            __stcg(&g_hbuf[wp][0][b0 + grow0][hb + gj0], (1.0f - z) * n + z * hm);
        }

        // ---- single grid barrier per step (phase1 -> phase2) ----
        // All cross-step hazards transitively ordered by this barrier (R5 matrix).
        __syncthreads();
        if (tid == 0) {
            __threadfence();
            atomicAdd(&g_bar, 1u);
            unsigned target = (unsigned)(t + 1) * R_GRID;
            while (*((volatile unsigned*)&g_bar) < target) __nanosleep(32);
            __threadfence();
        }
        __syncthreads();

        // ===== phase 2: layer 1 =====
        // inA = h0_new (no mask), inB = mask * h1_prev
        for (int idx = tid; idx < RB * HID / 4; idx += R_THREADS) {
            int row = idx >> 6, k4 = idx & 63;
            float4 v = __ldcg((const float4*)&g_hbuf[wp][0][b0 + row][k4 * 4]);
            *(float4*)&inA[row * INSTRIDE + k4 * 4] = v;
            float4 u = __ldcg((const float4*)&g_hbuf[rp][1][b0 + row][k4 * 4]);
            float m = smask[row];
            u.x *= m; u.y *= m; u.z *= m; u.w *= m;
            *(float4*)&inB[row * INSTRIDE + k4 * 4] = u;
        }
        __syncthreads();

        gemm_tile(inA, w1s, outA, b_ih1, hb, tid);   // gi1 tile
        gemm_tile(inB, w2s, outB, b_hh1, hb, tid);   // gh1 tile
        __syncthreads();

        // gates layer 1: one unit per thread
        {
            float gi_r = outA[grow0 * GSTRIDE + gj0];
            float gi_z = outA[grow0 * GSTRIDE + 16 + gj0];
            float gi_n = outA[grow0 * GSTRIDE + 32 + gj0];
            float gh_r = outB[grow0 * GSTRIDE + gj0];
            float gh_z = outB[grow0 * GSTRIDE + 16 + gj0];
            float gh_n = outB[grow0 * GSTRIDE + 32 + gj0];
            float r = sigmoidf_(gi_r + gh_r);
            float z = sigmoidf_(gi_z + gh_z);
            float n = tanhf(gi_n + r * gh_n);
            float hm = inB[grow0 * INSTRIDE + hb + gj0];     // masked h1_prev
            float hnew = (1.0f - z) * n + z * hm;
            __stcg(&g_hbuf[wp][1][b0 + grow0][hb + gj0], hnew);
            g_gruout[((size_t)t * BATCH + b0 + grow0) * HID + hb + gj0] = hnew;
        }
        __syncthreads();
    }
}

// ---------------- value head final reduction: v = hidden @ w_v2^T + b_v2 ----------------
__global__ void __launch_bounds__(256) vhead_kernel(
    const float* __restrict__ hidden, const float* __restrict__ w_v2,
    const float* __restrict__ b_v2, float* __restrict__ out)
{
    int row  = blockIdx.x * 8 + (threadIdx.x >> 5);
    int lane = threadIdx.x & 31;
    const float4* hp = (const float4*)(hidden + (size_t)row * HID);
    const float4* wp = (const float4*)w_v2;
    float s = 0.f;
#pragma unroll
    for (int i = 0; i < 2; i++) {
        float4 h4 = hp[lane * 2 + i];
        float4 w4 = __ldg(&wp[lane * 2 + i]);
        s += h4.x * w4.x + h4.y * w4.y + h4.z * w4.z + h4.w * w4.w;
    }
#pragma unroll
    for (int off = 16; off; off >>= 1) s += __shfl_xor_sync(0xffffffffu, s, off);
    if (lane == 0) out[row] = s + b_v2[0];
}

// ---------------- launch ----------------
extern "C" void kernel_launch(void* const* d_in, const int* in_sizes, int n_in,
                              void* d_out, int out_size) {
    const float* x        = (const float*)d_in[0];
    const int*   dones    = (const int*)  d_in[1];
    const float* h0       = (const float*)d_in[2];
    const float* w_shared = (const float*)d_in[3];
    const float* b_shared = (const float*)d_in[4];
    const float* w_ih     = (const float*)d_in[5];
    const float* w_hh     = (const float*)d_in[6];
    const float* b_ih     = (const float*)d_in[7];
    const float* b_hh     = (const float*)d_in[8];
    const float* w_v1     = (const float*)d_in[9];
    const float* b_v1     = (const float*)d_in[10];
    const float* w_v2     = (const float*)d_in[11];
    const float* b_v2     = (const float*)d_in[12];
    float* out = (float*)d_out;

    // idempotent, capture-safe (not a stream op)
    cudaFuncSetAttribute(recurrent_kernel,
                         cudaFuncAttributeMaxDynamicSharedMemorySize, R_SMEM_BYTES);

    float* featsP;  cudaGetSymbolAddress((void**)&featsP,  g_feats);
    float* gi0P;    cudaGetSymbolAddress((void**)&gi0P,    g_gi0);
    float* gruoutP; cudaGetSymbolAddress((void**)&gruoutP, g_gruout);
    float* hiddenP = featsP;   // overlay: feats is dead after gi0 GEMM

    // reset barrier + seed h ping-pong (parity 0) with h0
    init_bar_kernel<<<1, 1>>>();
    cudaMemcpyToSymbolAsync(g_hbuf, h0, (size_t)2 * BATCH * HID * sizeof(float),
                            0, cudaMemcpyDeviceToDevice, 0);

    // feats = LReLU(x @ w_shared^T + b_shared)  [131072, 256]
    {
        dim3 g(HID / 64, ROWS_TOT / 64);
        gemm_lin_kernel<true><<<g, 128>>>(x, w_shared, b_shared, featsP,
                                          ROWS_TOT, HID, FIN);
    }
    // gi0 = feats @ w_ih0^T + b_ih0  [131072, 768]
    {
        dim3 g(G3 / 64, ROWS_TOT / 64);
        gemm_lin_kernel<false><<<g, 128>>>(featsP, w_ih, b_ih, gi0P,
                                           ROWS_TOT, G3, HID);
    }
    // sequential GRU rollout (persistent, grid-resident)
    recurrent_kernel<<<R_GRID, R_THREADS, R_SMEM_BYTES>>>(dones, w_ih, w_hh, b_ih, b_hh);

    // hidden = LReLU(gruout @ w_v1^T + b_v1)   (overwrites g_feats)
    {
        dim3 g(HID / 64, ROWS_TOT / 64);
        gemm_lin_kernel<true><<<g, 128>>>(gruoutP, w_v1, b_v1, hiddenP,
                                          ROWS_TOT, HID, HID);
    }
    // v = hidden @ w_v2^T + b_v2  -> out[0 : 131072)
    vhead_kernel<<<ROWS_TOT / 8, 256>>>(hiddenP, w_v2, b_v2, out);

    // h_final lives in parity 0 after 512 steps -> out[131072 : 262144)
    if (out_size >= 2 * ROWS_TOT) {
        cudaMemcpyFromSymbolAsync(out + ROWS_TOT, g_hbuf,
                                  (size_t)2 * BATCH * HID * sizeof(float),
                                  0, cudaMemcpyDeviceToDevice, 0);
    }
}

// round 17
// speedup vs baseline: 2.1433x; 1.8718x over previous
#include <cuda_runtime.h>
#include <cuda_fp16.h>
#include <math.h>

// ---------------- problem constants ----------------
#define T_STEPS 512
#define BATCH   256
#define FIN     64
#define HID     256
#define G3      768
#define ROWS_TOT (T_STEPS*BATCH)   // 131072

// recurrent kernel partitioning
#define R_GRID    128        // 8 batch tiles x 16 hidden tiles
#define R_THREADS 512        // 16 warps (12 active per MMA gemm)
#define RB        32         // batch rows per CTA
#define WH_U      132        // fp16 row stride in uints (264 halfs)
#define GSTRIDE   50         // gate tile stride (EVEN: float2 stores at r*50+even col are 8B-aligned)

// smem words: 3 weight slices [48][WH_U] + 2 input tiles [32][WH_U] + 2 out tiles + mask
#define R_SMEM_WORDS (3*48*WH_U + 2*RB*WH_U + 2*RB*GSTRIDE + RB)
#define R_SMEM_BYTES (R_SMEM_WORDS*4)   // 122,752 B

// ---------------- device scratch (static: no allocs allowed) ----------------
__device__ float g_feats [(size_t)ROWS_TOT*HID];   // reused as value-net hidden
__device__ float g_gi0   [(size_t)ROWS_TOT*G3];    // layer0 gi incl b_ih0 (fp32, exact)
__device__ float g_gruout[(size_t)ROWS_TOT*HID];
__device__ float g_hbuf  [2][2][BATCH][HID];       // [parity][layer][B][H] ping-pong (fp32)
__device__ unsigned g_bar;

// ---------------- helpers ----------------
__device__ __forceinline__ float2 ffma2(float2 a, float2 b, float2 c) {
    unsigned long long au = *reinterpret_cast<unsigned long long*>(&a);
    unsigned long long bu = *reinterpret_cast<unsigned long long*>(&b);
    unsigned long long cu = *reinterpret_cast<unsigned long long*>(&c);
    unsigned long long du;
    asm("fma.rn.f32x2 %0, %1, %2, %3;" : "=l"(du) : "l"(au), "l"(bu), "l"(cu));
    return *reinterpret_cast<float2*>(&du);
}

__device__ __forceinline__ float sigmoidf_(float x) { return 1.0f / (1.0f + __expf(-x)); }

__device__ __forceinline__ unsigned pack_f16x2(float lo, float hi) {
    __half2 h = __floats2half2_rn(lo, hi);
    return *reinterpret_cast<unsigned*>(&h);
}

// m16n8k16 fp16 MMA, fp32 accumulate
__device__ __forceinline__ void mma16816(float& d0, float& d1, float& d2, float& d3,
                                         unsigned a0, unsigned a1, unsigned a2, unsigned a3,
                                         unsigned b0, unsigned b1) {
    asm volatile(
        "mma.sync.aligned.m16n8k16.row.col.f32.f16.f16.f32 "
        "{%0,%1,%2,%3}, {%4,%5,%6,%7}, {%8,%9}, {%0,%1,%2,%3};"
        : "+f"(d0), "+f"(d1), "+f"(d2), "+f"(d3)
        : "r"(a0), "r"(a1), "r"(a2), "r"(a3), "r"(b0), "r"(b1));
}

// local weight-row (0..47) -> global gate row for hidden base hb
__device__ __forceinline__ int grow_map(int hb, int c) {
    return (c < 16) ? (hb + c) : (c < 32) ? (256 + hb + (c - 16)) : (512 + hb + (c - 32));
}

__global__ void init_bar_kernel() { g_bar = 0u; }

// ---------------- generic tiled fp32 GEMM: C = act(A[M,K] @ W[N,K]^T + bias) ----------------
template <bool LRELU>
__global__ void __launch_bounds__(128) gemm_lin_kernel(
    const float* __restrict__ A, const float* __restrict__ W,
    const float* __restrict__ bias, float* __restrict__ C,
    int M, int N, int K)
{
    __shared__ __align__(16) float As[16][68];
    __shared__ __align__(16) float Bs[16][68];

    const int tid  = threadIdx.x;
    const int row0 = blockIdx.y * 64;
    const int col0 = blockIdx.x * 64;
    const int c0 = (tid & 15) * 4;
    const int r0 = (tid >> 4) * 8;

    float2 acc[4][4];
#pragma unroll
    for (int i = 0; i < 4; i++)
#pragma unroll
        for (int j = 0; j < 4; j++) acc[i][j] = make_float2(0.f, 0.f);

    for (int kt = 0; kt < K; kt += 16) {
#pragma unroll
        for (int i = 0; i < 2; i++) {
            int e  = tid + i * 128;
            int r  = e >> 2;
            int k4 = (e & 3) * 4;
            float4 va = *(const float4*)&A[(size_t)(row0 + r) * K + kt + k4];
            As[k4 + 0][r] = va.x; As[k4 + 1][r] = va.y; As[k4 + 2][r] = va.z; As[k4 + 3][r] = va.w;
            float4 vb = *(const float4*)&W[(size_t)(col0 + r) * K + kt + k4];
            Bs[k4 + 0][r] = vb.x; Bs[k4 + 1][r] = vb.y; Bs[k4 + 2][r] = vb.z; Bs[k4 + 3][r] = vb.w;
        }
        __syncthreads();
#pragma unroll
        for (int k = 0; k < 16; k++) {
            float4 a03 = *(const float4*)&As[k][r0];
            float4 a47 = *(const float4*)&As[k][r0 + 4];
            float4 b   = *(const float4*)&Bs[k][c0];
            float2 ap[4] = { make_float2(a03.x, a03.y), make_float2(a03.z, a03.w),
                             make_float2(a47.x, a47.y), make_float2(a47.z, a47.w) };
            float2 bd[4] = { make_float2(b.x, b.x), make_float2(b.y, b.y),
                             make_float2(b.z, b.z), make_float2(b.w, b.w) };
#pragma unroll
            for (int i = 0; i < 4; i++)
#pragma unroll
                for (int j = 0; j < 4; j++) acc[i][j] = ffma2(ap[i], bd[j], acc[i][j]);
        }
        __syncthreads();
    }

#pragma unroll
    for (int j = 0; j < 4; j++) {
        float bv = bias[col0 + c0 + j];
#pragma unroll
        for (int i = 0; i < 4; i++) {
            float v0 = acc[i][j].x + bv;
            float v1 = acc[i][j].y + bv;
            if (LRELU) { v0 = (v0 > 0.f) ? v0 : 0.01f * v0; v1 = (v1 > 0.f) ? v1 : 0.01f * v1; }
            C[(size_t)(row0 + r0 + 2 * i    ) * N + col0 + c0 + j] = v0;
            C[(size_t)(row0 + r0 + 2 * i + 1) * N + col0 + c0 + j] = v1;
        }
    }
}

// ---------------- recurrent tile GEMM via tensor cores ----------------
// out[32][48] = in[32][256] @ w[48][256]^T + bias ; fp16 operands, fp32 accumulate.
// 12 warps: warp w -> row tile mt=w&1 (rows mt*16..+15), col tile nt=w>>1 (cols nt*8..+7).
// 16 k-steps of m16n8k16. Fragments via plain LDS.32:
//   g=lane>>2, c=lane&3
//   a0=inH[mt16+g][2c+k0]      a1=inH[mt16+g+8][2c+k0]
//   a2=inH[mt16+g][2c+8+k0]    a3=inH[mt16+g+8][2c+8+k0]
//   b0=wH[nt8+g][2c+k0]        b1=wH[nt8+g][2c+8+k0]      (half2 each)
// D: d0=(g,2c) d1=(g,2c+1) d2=(g+8,2c) d3=(g+8,2c+1) -> float2 STS (GSTRIDE even => aligned).
__device__ __forceinline__ void gemm_tile_mma(const unsigned* __restrict__ inH,
                                              const unsigned* __restrict__ wH,
                                              float* __restrict__ out_s,
                                              float2 bias2, int tid)
{
    const int warp = tid >> 5;
    if (warp >= 12) return;
    const int lane = tid & 31;
    const int g = lane >> 2, c = lane & 3;
    const int mt = warp & 1, nt = warp >> 1;

    const unsigned* pa = inH + (size_t)(mt * 16 + g) * WH_U + c;
    const unsigned* pb = wH  + (size_t)(nt * 8  + g) * WH_U + c;

    float d0 = 0.f, d1 = 0.f, d2 = 0.f, d3 = 0.f;
#pragma unroll
    for (int kk = 0; kk < 16; kk++) {
        unsigned a0 = pa[kk * 8];
        unsigned a1 = pa[kk * 8 + 8 * WH_U];
        unsigned a2 = pa[kk * 8 + 4];
        unsigned a3 = pa[kk * 8 + 8 * WH_U + 4];
        unsigned b0 = pb[kk * 8];
        unsigned b1 = pb[kk * 8 + 4];
        mma16816(d0, d1, d2, d3, a0, a1, a2, a3, b0, b1);
    }

    const int r0 = mt * 16 + g, col = nt * 8 + 2 * c;
    *(float2*)&out_s[(r0    ) * GSTRIDE + col] = make_float2(d0 + bias2.x, d1 + bias2.y);
    *(float2*)&out_s[(r0 + 8) * GSTRIDE + col] = make_float2(d2 + bias2.x, d3 + bias2.y);
}

// ---------------- persistent recurrent kernel ----------------
__global__ void __launch_bounds__(R_THREADS, 1) recurrent_kernel(
    const int*   __restrict__ dones,
    const float* __restrict__ w_ih,   // [2][768][256]
    const float* __restrict__ w_hh,   // [2][768][256]
    const float* __restrict__ b_ih,   // [2][768]
    const float* __restrict__ b_hh)   // [2][768]
{
    extern __shared__ __align__(16) float smem[];
    unsigned* w0h = (unsigned*)smem;            // w_hh0 fp16 [48][WH_U]
    unsigned* w1h = w0h + 48 * WH_U;            // w_ih1
    unsigned* w2h = w1h + 48 * WH_U;            // w_hh1
    unsigned* inAh = w2h + 48 * WH_U;           // [32][WH_U] fp16
    unsigned* inBh = inAh + RB * WH_U;          // [32][WH_U] fp16
    float* outA  = (float*)(inBh + RB * WH_U);  // [32][GSTRIDE] fp32
    float* outB  = outA + RB * GSTRIDE;
    float* smask = outB + RB * GSTRIDE;         // [32]

    const int tid = threadIdx.x;
    const int bt  = blockIdx.x >> 4;
    const int ct  = blockIdx.x & 15;
    const int b0  = bt * RB;
    const int hb  = ct * 16;

    const float* w_hh0 = w_hh;
    const float* w_ih1 = w_ih + 768 * 256;
    const float* w_hh1 = w_hh + 768 * 256;

    // ---- stage + quantize persistent weight slices to fp16 ----
    for (int idx = tid; idx < 48 * 128; idx += R_THREADS) {
        int row = idx >> 7, u = idx & 127;
        int gr = grow_map(hb, row);
        float2 v0 = *(const float2*)&w_hh0[(size_t)gr * HID + u * 2];
        w0h[row * WH_U + u] = pack_f16x2(v0.x, v0.y);
        float2 v1 = *(const float2*)&w_ih1[(size_t)gr * HID + u * 2];
        w1h[row * WH_U + u] = pack_f16x2(v1.x, v1.y);
        float2 v2 = *(const float2*)&w_hh1[(size_t)gr * HID + u * 2];
        w2h[row * WH_U + u] = pack_f16x2(v2.x, v2.y);
    }

    // ---- hoist per-thread MMA biases (step-invariant; warps 0..11 only) ----
    const int warp = tid >> 5, lane = tid & 31;
    float2 bias0 = make_float2(0.f, 0.f), bias1 = bias0, bias2 = bias0;
    if (warp < 12) {
        int col = (warp >> 1) * 8 + 2 * (lane & 3);
        int ga = grow_map(hb, col), gb = grow_map(hb, col + 1);
        bias0 = make_float2(__ldg(&b_hh[ga]),       __ldg(&b_hh[gb]));
        bias1 = make_float2(__ldg(&b_ih[768 + ga]), __ldg(&b_ih[768 + gb]));
        bias2 = make_float2(__ldg(&b_hh[768 + ga]), __ldg(&b_hh[768 + gb]));
    }
    __syncthreads();

    // gate-unit mapping: 512 threads -> one (row, j) unit each
    const int grow0 = tid >> 4, gj0 = tid & 15;

    for (int t = 0; t < T_STEPS; t++) {
        const int rp = t & 1, wp = rp ^ 1;

        // ---- prefetch gi0 + raw h0_prev for this step's gate (stable pre-barrier) ----
        size_t gb0 = ((size_t)t * BATCH + b0 + grow0) * G3 + hb + gj0;
        float p_r0 = __ldcs(&g_gi0[gb0]);
        float p_z0 = __ldcs(&g_gi0[gb0 + 256]);
        float p_n0 = __ldcs(&g_gi0[gb0 + 512]);
        float h0raw = __ldcg(&g_hbuf[rp][0][b0 + grow0][hb + gj0]);

        // ---- done masks ----
        if (tid < RB) smask[tid] = 1.0f - (float)dones[t * BATCH + b0 + tid];
        __syncthreads();

        // ===== phase 1: layer 0 =====
        // stage inA = fp16(mask * h0_prev)
        for (int idx = tid; idx < RB * 128; idx += R_THREADS) {
            int row = idx >> 7, u = idx & 127;
            float2 v = __ldcg((const float2*)&g_hbuf[rp][0][b0 + row][u * 2]);
            float m = smask[row];
            inAh[row * WH_U + u] = pack_f16x2(v.x * m, v.y * m);
        }
        __syncthreads();

        gemm_tile_mma(inAh, w0h, outA, bias0, tid);   // gh0 tile
        __syncthreads();

        // gates layer 0 (hm from global fp32 -> state update stays exact)
        {
            float gh_r = outA[grow0 * GSTRIDE + gj0];
            float gh_z = outA[grow0 * GSTRIDE + 16 + gj0];
            float gh_n = outA[grow0 * GSTRIDE + 32 + gj0];
            float r = sigmoidf_(p_r0 + gh_r);
            float z = sigmoidf_(p_z0 + gh_z);
            float n = tanhf(p_n0 + r * gh_n);
            float hm = h0raw * smask[grow0];
            __stcg(&g_hbuf[wp][0][b0 + grow0][hb + gj0], (1.0f - z) * n + z * hm);
        }

        // ---- single grid barrier per step (phase1 -> phase2); R5 hazard matrix holds ----
        __syncthreads();
        if (tid == 0) {
            __threadfence();
            atomicAdd(&g_bar, 1u);
            unsigned target = (unsigned)(t + 1) * R_GRID;
            while (*((volatile unsigned*)&g_bar) < target) __nanosleep(32);
            __threadfence();
        }
        __syncthreads();

        // ===== phase 2: layer 1 =====
        // stage inA = fp16(h0_new), inB = fp16(mask * h1_prev); prefetch raw h1_prev
        float h1raw = __ldcg(&g_hbuf[rp][1][b0 + grow0][hb + gj0]);
        for (int idx = tid; idx < RB * 128; idx += R_THREADS) {
            int row = idx >> 7, u = idx & 127;
            float2 v = __ldcg((const float2*)&g_hbuf[wp][0][b0 + row][u * 2]);
            inAh[row * WH_U + u] = pack_f16x2(v.x, v.y);
            float2 uv = __ldcg((const float2*)&g_hbuf[rp][1][b0 + row][u * 2]);
            float m = smask[row];
            inBh[row * WH_U + u] = pack_f16x2(uv.x * m, uv.y * m);
        }
        __syncthreads();

        gemm_tile_mma(inAh, w1h, outA, bias1, tid);   // gi1 tile
        gemm_tile_mma(inBh, w2h, outB, bias2, tid);   // gh1 tile
        __syncthreads();

        // gates layer 1
        {
            float gi_r = outA[grow0 * GSTRIDE + gj0];
            float gi_z = outA[grow0 * GSTRIDE + 16 + gj0];
            float gi_n = outA[grow0 * GSTRIDE + 32 + gj0];
            float gh_r = outB[grow0 * GSTRIDE + gj0];
            float gh_z = outB[grow0 * GSTRIDE + 16 + gj0];
            float gh_n = outB[grow0 * GSTRIDE + 32 + gj0];
            float r = sigmoidf_(gi_r + gh_r);
            float z = sigmoidf_(gi_z + gh_z);
            float n = tanhf(gi_n + r * gh_n);
            float hm = h1raw * smask[grow0];
            float hnew = (1.0f - z) * n + z * hm;
            __stcg(&g_hbuf[wp][1][b0 + grow0][hb + gj0], hnew);
            g_gruout[((size_t)t * BATCH + b0 + grow0) * HID + hb + gj0] = hnew;
        }
        __syncthreads();
    }
}

// ---------------- value head final reduction: v = hidden @ w_v2^T + b_v2 ----------------
__global__ void __launch_bounds__(256) vhead_kernel(
    const float* __restrict__ hidden, const float* __restrict__ w_v2,
    const float* __restrict__ b_v2, float* __restrict__ out)
{
    int row  = blockIdx.x * 8 + (threadIdx.x >> 5);
    int lane = threadIdx.x & 31;
    const float4* hp = (const float4*)(hidden + (size_t)row * HID);
    const float4* wp = (const float4*)w_v2;
    float s = 0.f;
#pragma unroll
    for (int i = 0; i < 2; i++) {
        float4 h4 = hp[lane * 2 + i];
        float4 w4 = __ldg(&wp[lane * 2 + i]);
        s += h4.x * w4.x + h4.y * w4.y + h4.z * w4.z + h4.w * w4.w;
    }
#pragma unroll
    for (int off = 16; off; off >>= 1) s += __shfl_xor_sync(0xffffffffu, s, off);
    if (lane == 0) out[row] = s + b_v2[0];
}

// ---------------- launch ----------------
extern "C" void kernel_launch(void* const* d_in, const int* in_sizes, int n_in,
                              void* d_out, int out_size) {
    const float* x        = (const float*)d_in[0];
    const int*   dones    = (const int*)  d_in[1];
    const float* h0       = (const float*)d_in[2];
    const float* w_shared = (const float*)d_in[3];
    const float* b_shared = (const float*)d_in[4];
    const float* w_ih     = (const float*)d_in[5];
    const float* w_hh     = (const float*)d_in[6];
    const float* b_ih     = (const float*)d_in[7];
    const float* b_hh     = (const float*)d_in[8];
    const float* w_v1     = (const float*)d_in[9];
    const float* b_v1     = (const float*)d_in[10];
    const float* w_v2     = (const float*)d_in[11];
    const float* b_v2     = (const float*)d_in[12];
    float* out = (float*)d_out;

    // idempotent, capture-safe (not a stream op)
    cudaFuncSetAttribute(recurrent_kernel,
                         cudaFuncAttributeMaxDynamicSharedMemorySize, R_SMEM_BYTES);

    float* featsP;  cudaGetSymbolAddress((void**)&featsP,  g_feats);
    float* gi0P;    cudaGetSymbolAddress((void**)&gi0P,    g_gi0);
    float* gruoutP; cudaGetSymbolAddress((void**)&gruoutP, g_gruout);
    float* hiddenP = featsP;   // overlay: feats is dead after gi0 GEMM

    // reset barrier + seed h ping-pong (parity 0) with h0
    init_bar_kernel<<<1, 1>>>();
    cudaMemcpyToSymbolAsync(g_hbuf, h0, (size_t)2 * BATCH * HID * sizeof(float),
                            0, cudaMemcpyDeviceToDevice, 0);

    // feats = LReLU(x @ w_shared^T + b_shared)  [131072, 256]
    {
        dim3 g(HID / 64, ROWS_TOT / 64);
        gemm_lin_kernel<true><<<g, 128>>>(x, w_shared, b_shared, featsP,
                                          ROWS_TOT, HID, FIN);
    }
    // gi0 = feats @ w_ih0^T + b_ih0  [131072, 768]
    {
        dim3 g(G3 / 64, ROWS_TOT / 64);
        gemm_lin_kernel<false><<<g, 128>>>(featsP, w_ih, b_ih, gi0P,
                                           ROWS_TOT, G3, HID);
    }
    // sequential GRU rollout (persistent, grid-resident)
    recurrent_kernel<<<R_GRID, R_THREADS, R_SMEM_BYTES>>>(dones, w_ih, w_hh, b_ih, b_hh);

    // hidden = LReLU(gruout @ w_v1^T + b_v1)   (overwrites g_feats)
    {
        dim3 g(HID / 64, ROWS_TOT / 64);
        gemm_lin_kernel<true><<<g, 128>>>(gruoutP, w_v1, b_v1, hiddenP,
                                          ROWS_TOT, HID, HID);
    }
    // v = hidden @ w_v2^T + b_v2  -> out[0 : 131072)
    vhead_kernel<<<ROWS_TOT / 8, 256>>>(hiddenP, w_v2, b_v2, out);

    // h_final lives in parity 0 after 512 steps -> out[131072 : 262144)
    if (out_size >= 2 * ROWS_TOT) {
        cudaMemcpyFromSymbolAsync(out + ROWS_TOT, g_hbuf,
                                  (size_t)2 * BATCH * HID * sizeof(float),
                                  0, cudaMemcpyDeviceToDevice, 0);
    }
}